// round 14
// baseline (speedup 1.0000x reference)
#include <cuda_runtime.h>
#include <cuda_bf16.h>
#include <cstdint>
#include <math.h>

// Problem constants
#define SEQQ   1024
#define BSZ    8
#define EMBED  1024
#define KDIM   64
#define NDIM   16
#define NR     16384
#define HCH    64

// ---------------- scratch (device globals; no allocations) ----------------
__device__ float g_Ls[4 * 1024];
__device__ float g_Bsig[2 * 1024];
__device__ int   g_E[2 * NR * 4];
__device__ int   g_Col[2 * NR];
__device__ float g_Coef[2 * NR];
__device__ float g_w[SEQQ * KDIM * 32];
__device__ float g_Cc[KDIM * HCH * 32];
__device__ float g_ktmp[HCH * KDIM * SEQQ];
__device__ float g_ksum[EMBED * SEQQ];      // [e][di*32+dj]
__device__ float g_xT[EMBED * 256 * 32];    // [e][m=i*8+b][q]
__device__ float g_yT[EMBED * 256 * 32];    // [e][m][j]

__device__ __forceinline__ float ex2_approx(float e) {
    float r; asm("ex2.approx.ftz.f32 %0, %1;" : "=f"(r) : "f"(e)); return r;
}
// mma.sync m16n8k16 bf16 -> fp32 accumulate (base sm_80+ PTX; no 'a' target)
__device__ __forceinline__ void mma16816(float* c, const uint32_t* a,
                                         const uint32_t* b) {
    asm volatile(
        "mma.sync.aligned.m16n8k16.row.col.f32.bf16.bf16.f32 "
        "{%0,%1,%2,%3}, {%4,%5,%6,%7}, {%8,%9}, {%0,%1,%2,%3};\n"
        : "+f"(c[0]), "+f"(c[1]), "+f"(c[2]), "+f"(c[3])
        : "r"(a[0]), "r"(a[1]), "r"(a[2]), "r"(a[3]), "r"(b[0]), "r"(b[1]));
}

// ---------------- stage 1+2: prep + decode ----------------
__global__ void k_init(const float* __restrict__ A,
                       const float* __restrict__ B1,
                       const float* __restrict__ B2,
                       const float* __restrict__ C1,
                       const float* __restrict__ C2,
                       const float* __restrict__ M) {
    int bb = blockIdx.x;
    if (bb < 512) {
        int idx = bb * 256 + threadIdx.x;
        if (idx < 4096) {
            float s = 1.0f / (1.0f + expf(-A[idx]));
            g_Ls[idx] = log2f(s);
        } else if (idx < 5120) {
            int t = idx - 4096;
            g_Bsig[t] = 1.0f / (1.0f + expf(-B1[t]));
        } else if (idx < 6144) {
            int t = idx - 5120;
            g_Bsig[1024 + t] = 1.0f / (1.0f + expf(-B2[t]));
        }
        if (idx < KDIM * HCH * 32) {
            int kd = idx >> 11;
            int hh = (idx >> 5) & 63;
            int dn = idx & 31;
            int d = dn >> 4, n = dn & 15;
            const float* C = d ? C2 : C1;
            g_Cc[idx] = 0.25f * C[(hh * 64 + kd) * 16 + n];
        }
    } else {
        int t = (bb - 512) * 256 + threadIdx.x;
        if (t >= 2 * 5 * NR) return;
        const float4* m4 = reinterpret_cast<const float4*>(M + (size_t)t * 64);
        int idx = 0; float val = 0.0f;
#pragma unroll
        for (int i = 0; i < 16; i++) {
            float4 v = m4[i];
            if (v.x != 0.0f) { idx = 4 * i + 0; val = v.x; }
            if (v.y != 0.0f) { idx = 4 * i + 1; val = v.y; }
            if (v.z != 0.0f) { idx = 4 * i + 2; val = v.z; }
            if (v.w != 0.0f) { idx = 4 * i + 3; val = v.w; }
        }
        int d   = t / (5 * NR);
        int rem = t - d * (5 * NR);
        int a   = rem / NR;
        int r   = rem - a * NR;
        if (a < 4) g_E[(d * NR + r) * 4 + a] = idx;
        else { g_Col[d * NR + r] = idx; g_Coef[d * NR + r] = val; }
    }
}

// ---------------- stage 3: w via MUFU exp2 ----------------
__global__ void k_w() {
    __shared__ float se[64];
    __shared__ float scoef[16];
    __shared__ int   scol[16];
    int d = blockIdx.x >> 10;
    int p = blockIdx.x & 1023;
    int tid = threadIdx.x;
    if (tid < 64) {
        int r2 = tid >> 2, a = tid & 3;
        se[tid] = (float)g_E[(d * NR + p * 16 + r2) * 4 + a];
    } else if (tid < 80) {
        scoef[tid - 64] = g_Coef[d * NR + p * 16 + (tid - 64)];
    } else if (tid < 96) {
        scol[tid - 80] = g_Col[d * NR + p * 16 + (tid - 80)];
    }
    __syncthreads();
    int kn = tid;
    float ls0 = g_Ls[kn], ls1 = g_Ls[1024 + kn];
    float ls2 = g_Ls[2048 + kn], ls3 = g_Ls[3072 + kn];
    float b0 = g_Bsig[kn], b1 = g_Bsig[1024 + kn];
    float acc = 0.0f;
#pragma unroll
    for (int r2 = 0; r2 < 16; r2++) {
        float E = se[r2 * 4 + 0] * ls0 + se[r2 * 4 + 1] * ls1
                + se[r2 * 4 + 2] * ls2 + se[r2 * 4 + 3] * ls3;
        acc += ex2_approx(E) * scoef[r2] * (scol[r2] ? b1 : b0);
    }
    g_w[(p * 64 + (kn >> 4)) * 32 + d * 16 + (kn & 15)] = acc;
}

// ---------------- stage 4: 64 small GEMMs -> ktmp ----------------
__global__ __launch_bounds__(256) void k_gemm() {
    __shared__ float Cs[2048];
    __shared__ float ws[64 * 33];
    int kd = blockIdx.x & 63;
    int p0 = (blockIdx.x >> 6) * 64;
    int tid = threadIdx.x;
    for (int idx = tid; idx < 2048; idx += 256)
        Cs[idx] = g_Cc[kd * 2048 + idx];
    for (int idx = tid; idx < 2048; idx += 256) {
        int pl = idx >> 5, dn = idx & 31;
        ws[pl * 33 + dn] = g_w[((size_t)(p0 + pl) * 64 + kd) * 32 + dn];
    }
    __syncthreads();
    int tp = tid & 31;
    int h0 = (tid >> 5) * 8;
    float acc[2][8];
#pragma unroll
    for (int i = 0; i < 2; i++)
#pragma unroll
        for (int j = 0; j < 8; j++) acc[i][j] = 0.0f;
#pragma unroll 8
    for (int dn = 0; dn < 32; dn++) {
        float cv[8];
#pragma unroll
        for (int j = 0; j < 8; j++) cv[j] = Cs[(h0 + j) * 32 + dn];
#pragma unroll
        for (int i = 0; i < 2; i++) {
            float wv = ws[(tp + 32 * i) * 33 + dn];
#pragma unroll
            for (int j = 0; j < 8; j++) acc[i][j] += wv * cv[j];
        }
    }
#pragma unroll
    for (int j = 0; j < 8; j++)
#pragma unroll
        for (int i = 0; i < 2; i++)
            g_ktmp[((h0 + j) * 64 + kd) * 1024 + p0 + tp + 32 * i] = acc[i][j];
}

// ---------------- stage 5: boundary scale + flip-sum ----------------
__device__ __forceinline__ float bscale(int i, int j) {
    return ((i == 0) != (j == 0)) ? 2.0f : 1.0f;
}
__global__ void k_asm() {
    int e = blockIdx.x;
    int h = e >> 4, ns = e & 15;
    const float* b0 = g_ktmp + (h * 64 +  0 + ns) * 1024;
    const float* b1 = g_ktmp + (h * 64 + 16 + ns) * 1024;
    const float* b2 = g_ktmp + (h * 64 + 32 + ns) * 1024;
    const float* b3 = g_ktmp + (h * 64 + 48 + ns) * 1024;
    for (int pos = threadIdx.x; pos < 1024; pos += 256) {
        int i = pos >> 5, j = pos & 31;
        int fi = 31 - i, fj = 31 - j;
        float v = bscale(i,  j)  * b0[i  * 32 + j ]
                + bscale(fi, j)  * b1[fi * 32 + j ]
                + bscale(i,  fj) * b2[i  * 32 + fj]
                + bscale(fi, fj) * b3[fi * 32 + fj];
        g_ksum[e * 1024 + pos] = v;
    }
}

// ---------------- stage 6a: transpose x -> g_xT[e][m=i*8+b][q] ----------------
// XOR-swizzled smem: both phases coalesced in gmem and conflict-free in smem.
__global__ __launch_bounds__(256) void t_in(const float* __restrict__ x) {
    __shared__ float s[8192];
    int i = blockIdx.x >> 5, e0 = (blockIdx.x & 31) * 32;
    int tid = threadIdx.x;
#pragma unroll 8
    for (int p = 0; p < 32; p++) {
        int idx = p * 256 + tid;          // = q*256 + b*32 + ep
        int ep = idx & 31, b = (idx >> 5) & 7, q = idx >> 8;
        s[ep * 256 + ((b * 32 + q) ^ ep)] =
            x[(size_t)(i * 32 + q) * 8192 + b * 1024 + e0 + ep];
    }
    __syncthreads();
#pragma unroll 8
    for (int p = 0; p < 32; p++) {
        int idx = p * 256 + tid;          // = ep*256 + b*32 + q
        int q = idx & 31, b = (idx >> 5) & 7, ep = idx >> 8;
        g_xT[(size_t)(e0 + ep) * 8192 + (i * 8 + b) * 32 + q] =
            s[ep * 256 + ((b * 32 + q) ^ ep)];
    }
}

// ---------------- stage 6b: tensor-core conv via mma.sync ----------------
// CTA = channel e. Causal 2D conv == sum over row-shifts di of
//   Y[m, j] += X[m - 8*di, q] * T_di[j, q],  T_di[j,q] = k_e[di, j-q] (q<=j).
// X buffer: 248 zero rows + 256 data rows of 32 bf16, row stride 80 B
// (conflict-free fragment loads). hi/lo bf16 split planes; 3 groups
// (hh, hl, lh) accumulate into shared fp32 fragments (~1e-5 rel err).
// Warp w owns m-tiles {w, 15-w}: shift-skip (di <= 2*mt+1) gives exactly
// 34 tile-shifts per warp -> perfectly balanced. 816 mma.sync per warp.
#define XS     80
#define XLO    40320
#define TBASE  80640
#define TLOOFF 65536
#define CMM_SMEM 211712

__global__ void __launch_bounds__(256, 1) k_convmma() {
    extern __shared__ __align__(128) char sm[];
    int e = blockIdx.x;
    int tid = threadIdx.x, w = tid >> 5, lane = tid & 31;
    int gid = lane >> 2, lid4 = lane & 3;

    // zero the 248 pad rows of both X planes (disjoint from data fill)
    for (int i = tid; i < 4960; i += 256) {
        reinterpret_cast<uint32_t*>(sm)[i] = 0;
        reinterpret_cast<uint32_t*>(sm + XLO)[i] = 0;
    }
    // fill X data rows (hi/lo split)
    const float* xs = g_xT + (size_t)e * 8192;
    for (int idx = tid; idx < 8192; idx += 256) {
        float v = xs[idx];
        int m = idx >> 5, q = idx & 31;
        __nv_bfloat16 h = __float2bfloat16_rn(v);
        __nv_bfloat16 l = __float2bfloat16_rn(v - __bfloat162float(h));
        int off = (248 + m) * XS + q * 2;
        *reinterpret_cast<__nv_bfloat16*>(sm + off) = h;
        *reinterpret_cast<__nv_bfloat16*>(sm + XLO + off) = l;
    }
    // fill Toeplitz tiles (row stride 64 B)
    const float* ke = g_ksum + (size_t)e * 1024;
    for (int idx = tid; idx < 32768; idx += 256) {
        int di = idx >> 10, j = (idx >> 5) & 31, q = idx & 31;
        float v = (q <= j) ? ke[di * 32 + (j - q)] : 0.0f;
        __nv_bfloat16 h = __float2bfloat16_rn(v);
        __nv_bfloat16 l = __float2bfloat16_rn(v - __bfloat162float(h));
        int off = TBASE + di * 2048 + j * 64 + q * 2;
        *reinterpret_cast<__nv_bfloat16*>(sm + off) = h;
        *reinterpret_cast<__nv_bfloat16*>(sm + off + TLOOFF) = l;
    }
    __syncthreads();

    int mtA = w, mtB = 15 - w;
    int dmA = 2 * mtA + 1;
    int dmB = 2 * mtB + 1; if (dmB > 31) dmB = 31;
    int dmax = (dmA > dmB) ? dmA : dmB; if (dmax > 31) dmax = 31;

    float c[2][4][4];
#pragma unroll
    for (int t = 0; t < 2; t++)
#pragma unroll
        for (int nt = 0; nt < 4; nt++)
#pragma unroll
            for (int r = 0; r < 4; r++) c[t][nt][r] = 0.0f;

    for (int di = 0; di <= dmax; di++) {
        // B fragments for this shift (hi & lo)
        uint32_t bh[4][2][2], bl[4][2][2];
        const char* tb = sm + TBASE + di * 2048;
#pragma unroll
        for (int nt = 0; nt < 4; nt++) {
            int ro = (nt * 8 + gid) * 64;
#pragma unroll
            for (int kt = 0; kt < 2; kt++) {
                int co = ro + (kt * 16 + lid4 * 2) * 2;
                bh[nt][kt][0] = *reinterpret_cast<const uint32_t*>(tb + co);
                bh[nt][kt][1] = *reinterpret_cast<const uint32_t*>(tb + co + 16);
                bl[nt][kt][0] = *reinterpret_cast<const uint32_t*>(tb + co + TLOOFF);
                bl[nt][kt][1] = *reinterpret_cast<const uint32_t*>(tb + co + 16 + TLOOFF);
            }
        }
#pragma unroll
        for (int t = 0; t < 2; t++) {
            int mt = t ? mtB : mtA;
            if (di > 2 * mt + 1) continue;
            int rb = 248 + 16 * mt - 8 * di;
#pragma unroll
            for (int kt = 0; kt < 2; kt++) {
                const char* xa = sm + (rb + gid) * XS + (kt * 16 + lid4 * 2) * 2;
                uint32_t ah[4], al[4];
                ah[0] = *reinterpret_cast<const uint32_t*>(xa);
                ah[1] = *reinterpret_cast<const uint32_t*>(xa + 8 * XS);
                ah[2] = *reinterpret_cast<const uint32_t*>(xa + 16);
                ah[3] = *reinterpret_cast<const uint32_t*>(xa + 8 * XS + 16);
                al[0] = *reinterpret_cast<const uint32_t*>(xa + XLO);
                al[1] = *reinterpret_cast<const uint32_t*>(xa + XLO + 8 * XS);
                al[2] = *reinterpret_cast<const uint32_t*>(xa + XLO + 16);
                al[3] = *reinterpret_cast<const uint32_t*>(xa + XLO + 8 * XS + 16);
#pragma unroll
                for (int nt = 0; nt < 4; nt++) {
                    mma16816(c[t][nt], ah, bh[nt][kt]);   // hh
                    mma16816(c[t][nt], ah, bl[nt][kt]);   // hl
                    mma16816(c[t][nt], al, bh[nt][kt]);   // lh
                }
            }
        }
    }

    // epilogue: fragment layout c0:(row gid, col lid4*2), c1:+1, c2/c3:row+8
    float* yd = g_yT + (size_t)e * 8192;
#pragma unroll
    for (int t = 0; t < 2; t++) {
        int mt = t ? mtB : mtA;
#pragma unroll
        for (int nt = 0; nt < 4; nt++) {
            int m0 = 16 * mt + gid;
            int j0 = nt * 8 + lid4 * 2;
            *reinterpret_cast<float2*>(yd + m0 * 32 + j0) =
                make_float2(c[t][nt][0], c[t][nt][1]);
            *reinterpret_cast<float2*>(yd + (m0 + 8) * 32 + j0) =
                make_float2(c[t][nt][2], c[t][nt][3]);
        }
    }
}

// ---------------- stage 6c: transpose back + residual ----------------
__global__ __launch_bounds__(256) void t_out(const float* __restrict__ x,
                                             const float* __restrict__ omega,
                                             float* __restrict__ out) {
    __shared__ float s[8192];
    int i = blockIdx.x >> 5, e0 = (blockIdx.x & 31) * 32;
    int tid = threadIdx.x;
#pragma unroll 8
    for (int p = 0; p < 32; p++) {
        int idx = p * 256 + tid;          // = ep*256 + b*32 + j
        int j = idx & 31, b = (idx >> 5) & 7, ep = idx >> 8;
        s[ep * 256 + ((b * 32 + j) ^ ep)] =
            g_yT[(size_t)(e0 + ep) * 8192 + (i * 8 + b) * 32 + j];
    }
    __syncthreads();
#pragma unroll 8
    for (int p = 0; p < 32; p++) {
        int idx = p * 256 + tid;          // = q*256 + b*32 + ep
        int ep = idx & 31, b = (idx >> 5) & 7, q = idx >> 8;
        size_t ga = (size_t)(i * 32 + q) * 8192 + b * 1024 + e0 + ep;
        out[ga] = s[ep * 256 + ((b * 32 + q) ^ ep)] + omega[e0 + ep] * x[ga];
    }
}

// ---------------- launch ----------------
extern "C" void kernel_launch(void* const* d_in, const int* in_sizes, int n_in,
                              void* d_out, int out_size) {
    const float* x     = (const float*)d_in[0];
    const float* A     = (const float*)d_in[1];
    const float* B1    = (const float*)d_in[2];
    const float* B2    = (const float*)d_in[3];
    const float* C1    = (const float*)d_in[4];
    const float* C2    = (const float*)d_in[5];
    const float* omega = (const float*)d_in[6];
    const float* onem  = (const float*)d_in[7];
    float* out = (float*)d_out;

    // idempotent, deterministic on every call (no static guards)
    cudaFuncSetAttribute(k_convmma,
                         cudaFuncAttributeMaxDynamicSharedMemorySize, CMM_SMEM);

    k_init   <<<1152, 256>>>(A, B1, B2, C1, C2, onem);
    t_in     <<<1024, 256>>>(x);
    k_w      <<<2048, 1024>>>();
    k_gemm   <<<1024, 256>>>();
    k_asm    <<<1024, 256>>>();
    k_convmma<<<1024, 256, CMM_SMEM>>>();
    t_out    <<<1024, 256>>>(x, omega, out);
}

// round 15
// speedup vs baseline: 1.3907x; 1.3907x over previous
#include <cuda_runtime.h>
#include <math.h>

// Problem constants
#define SEQQ   1024      // L_SIDE*L_SIDE
#define BSZ    8
#define EMBED  1024
#define KDIM   64        // kernel_dim = DIRS * N_SSM
#define NDIM   16
#define NR     16384     // R per flow axis (SEQ * R2)
#define HCH    64        // EMBED / N_SSM

// ---------------- scratch (device globals; no allocations) ----------------
__device__ float g_Ls[4 * 1024];        // log2(sigmoid(A))  [a][kd*16+n]
__device__ float g_Bsig[2 * 1024];      // sigmoid(B1/B2)    [c][kd*16+n]
__device__ int   g_E[2 * NR * 4];       // one-hot power indices per (d,r,a)
__device__ int   g_Col[2 * NR];         // B column select (0/1)
__device__ float g_Coef[2 * NR];        // integer coefficient
__device__ float g_w[SEQQ * KDIM * 32]; // w  [p][kd][dn] , dn = d*16+n
__device__ float g_Cc[KDIM * HCH * 32]; // Ccat [kd][h][dn] (x0.25 folded)
__device__ float g_ktmp[HCH * KDIM * SEQQ]; // [h][kd][p]
__device__ float g_ksum[EMBED * SEQQ];  // summed+flipped kernel [e][pos]

__device__ __forceinline__ float ex2_approx(float e) {
    float r; asm("ex2.approx.ftz.f32 %0, %1;" : "=f"(r) : "f"(e)); return r;
}

// ---------------- stage 1+2 merged: prep (sigmoids/logs/Ccat) + decode ----------------
__global__ void k_init(const float* __restrict__ A,
                       const float* __restrict__ B1,
                       const float* __restrict__ B2,
                       const float* __restrict__ C1,
                       const float* __restrict__ C2,
                       const float* __restrict__ M) {
    int bb = blockIdx.x;
    if (bb < 512) {
        int idx = bb * 256 + threadIdx.x;
        if (idx < 4096) {
            float s = 1.0f / (1.0f + expf(-A[idx]));    // A layout (4,64,16)
            g_Ls[idx] = log2f(s);
        } else if (idx < 5120) {
            int t = idx - 4096;
            g_Bsig[t] = 1.0f / (1.0f + expf(-B1[t]));
        } else if (idx < 6144) {
            int t = idx - 5120;
            g_Bsig[1024 + t] = 1.0f / (1.0f + expf(-B2[t]));
        }
        if (idx < KDIM * HCH * 32) {                    // 131072
            int kd = idx >> 11;
            int hh = (idx >> 5) & 63;
            int dn = idx & 31;
            int d = dn >> 4, n = dn & 15;
            const float* C = d ? C2 : C1;
            g_Cc[idx] = 0.25f * C[(hh * 64 + kd) * 16 + n];  // scale=1/sqrt(16)
        }
    } else {
        int t = (bb - 512) * 256 + threadIdx.x;          // (d,a,r) flattened
        if (t >= 2 * 5 * NR) return;
        const float4* m4 = reinterpret_cast<const float4*>(M + (size_t)t * 64);
        int idx = 0; float val = 0.0f;
#pragma unroll
        for (int i = 0; i < 16; i++) {
            float4 v = m4[i];
            if (v.x != 0.0f) { idx = 4 * i + 0; val = v.x; }
            if (v.y != 0.0f) { idx = 4 * i + 1; val = v.y; }
            if (v.z != 0.0f) { idx = 4 * i + 2; val = v.z; }
            if (v.w != 0.0f) { idx = 4 * i + 3; val = v.w; }
        }
        int d   = t / (5 * NR);
        int rem = t - d * (5 * NR);
        int a   = rem / NR;
        int r   = rem - a * NR;
        if (a < 4) {
            g_E[(d * NR + r) * 4 + a] = idx;
        } else {
            g_Col[d * NR + r]  = idx;
            g_Coef[d * NR + r] = val;
        }
    }
}

// ---------------- stage 3: w[d,p,k,n] via MUFU exp2 of summed log-powers ----------------
__global__ void k_w() {
    __shared__ float se[64];
    __shared__ float scoef[16];
    __shared__ int   scol[16];
    int d = blockIdx.x >> 10;
    int p = blockIdx.x & 1023;
    int tid = threadIdx.x;
    if (tid < 64) {
        int r2 = tid >> 2, a = tid & 3;
        se[tid] = (float)g_E[(d * NR + p * 16 + r2) * 4 + a];
    } else if (tid < 80) {
        scoef[tid - 64] = g_Coef[d * NR + p * 16 + (tid - 64)];
    } else if (tid < 96) {
        scol[tid - 80] = g_Col[d * NR + p * 16 + (tid - 80)];
    }
    __syncthreads();
    int kn = tid;                       // 1024 threads = (kd,n)
    float ls0 = g_Ls[kn], ls1 = g_Ls[1024 + kn];
    float ls2 = g_Ls[2048 + kn], ls3 = g_Ls[3072 + kn];
    float b0 = g_Bsig[kn], b1 = g_Bsig[1024 + kn];
    float acc = 0.0f;
#pragma unroll
    for (int r2 = 0; r2 < 16; r2++) {
        float E = se[r2 * 4 + 0] * ls0 + se[r2 * 4 + 1] * ls1
                + se[r2 * 4 + 2] * ls2 + se[r2 * 4 + 3] * ls3;
        float term = ex2_approx(E) * scoef[r2] * (scol[r2] ? b1 : b0);
        acc += term;
    }
    g_w[(p * 64 + (kn >> 4)) * 32 + d * 16 + (kn & 15)] = acc;
}

// ---------------- stage 4: 64 small GEMMs -> ktmp[h][kd][p] ----------------
// 2048 blocks = 64 kd x 32 p-tiles(32). Half the per-thread work of the old
// version -> 2x concurrent blocks, shorter latency tail (was 22us @ issue 33%).
__global__ __launch_bounds__(256) void k_gemm() {
    __shared__ float Cs[2048];        // [h][dn]  (broadcast reads -> no pad)
    __shared__ float ws[32 * 33];     // [pl][dn] stride-33 pad
    int kd = blockIdx.x & 63;
    int p0 = (blockIdx.x >> 6) * 32;
    int tid = threadIdx.x;
    for (int idx = tid; idx < 2048; idx += 256)
        Cs[idx] = g_Cc[kd * 2048 + idx];
    for (int idx = tid; idx < 1024; idx += 256) {
        int pl = idx >> 5, dn = idx & 31;
        ws[pl * 33 + dn] = g_w[((size_t)(p0 + pl) * 64 + kd) * 32 + dn];
    }
    __syncthreads();
    int tp = tid & 31;                 // p = p0 + tp
    int h0 = (tid >> 5) * 8;
    float acc[8];
#pragma unroll
    for (int j = 0; j < 8; j++) acc[j] = 0.0f;
#pragma unroll 8
    for (int dn = 0; dn < 32; dn++) {
        float wv = ws[tp * 33 + dn];
#pragma unroll
        for (int j = 0; j < 8; j++) acc[j] += wv * Cs[(h0 + j) * 32 + dn];
    }
#pragma unroll
    for (int j = 0; j < 8; j++)
        g_ktmp[((h0 + j) * 64 + kd) * 1024 + p0 + tp] = acc[j];
}

// ---------------- stage 5: boundary scale + 4-direction flip-sum ----------------
__device__ __forceinline__ float bscale(int i, int j) {
    // row0 x2, col0 x2, corner /4 => corner net 1, edges 2, interior 1
    return ((i == 0) != (j == 0)) ? 2.0f : 1.0f;
}
__global__ void k_asm() {
    int e = blockIdx.x;
    int h = e >> 4, ns = e & 15;
    const float* b0 = g_ktmp + (h * 64 +  0 + ns) * 1024;
    const float* b1 = g_ktmp + (h * 64 + 16 + ns) * 1024;
    const float* b2 = g_ktmp + (h * 64 + 32 + ns) * 1024;
    const float* b3 = g_ktmp + (h * 64 + 48 + ns) * 1024;
    for (int pos = threadIdx.x; pos < 1024; pos += 256) {
        int i = pos >> 5, j = pos & 31;
        int fi = 31 - i, fj = 31 - j;
        float v = bscale(i,  j)  * b0[i  * 32 + j ]
                + bscale(fi, j)  * b1[fi * 32 + j ]
                + bscale(i,  fj) * b2[i  * 32 + fj]
                + bscale(fi, fj) * b3[fi * 32 + fj];
        g_ksum[e * 1024 + pos] = v;
    }
}

// ---------------- stage 6: causal 2D conv (complementary-mask packed) ----------------
// Warp = (channel e, batch pair A=b0, B=b0+1). Prepass: all lanes do image-A
// shift 0 on their own row. Main loop di=1..32: lanes >= di continue image-A
// row `lane` at shift di; lanes < di work image-B row (31-lane) at shift
// (32-di). Active masks are exact complements -> zero idle lanes; kernel rows
// (di for A, 32-di for B) are warp-uniform-per-group -> 2-address LDG.128.
// Lane lane==di-1 switches A->B at iteration di: flush A row into the A-image
// slot (32-di) freed this very iteration, zero accumulators. Residual is added
// at writeback from a fresh coalesced x read.
// __launch_bounds__(64, 9): cap regs at ~113 so 9 blocks (18 warps/SM) fit the
// register file — the previous build was register-capped at ~6 blocks
// (12 warps/SM, 3/SMSP), leaving the FFMA pipe at ~50% efficiency.
__global__ __launch_bounds__(64, 9) void k_conv(const float* __restrict__ x,
                                                const float* __restrict__ omega,
                                                float* __restrict__ out) {
    __shared__ float sx[2 * 2112];     // 2 channels x (2 images x 32x33)
    int gb = blockIdx.x;               // 2048 = 4 bpairs x 512 e-pairs
    int bp = gb >> 9;
    int e0 = (gb & 511) * 2;
    int b0 = bp * 2;
    int tid = threadIdx.x;
    int ww = tid >> 5, lane = tid & 31;

    // stage x: x[pos][b][e] -> sx[ee][bs][row][q]
    for (int idx = tid; idx < 4096; idx += 64) {
        int ee = idx & 1, bs = (idx >> 1) & 1, pos = idx >> 2;
        int row = pos >> 5, q = pos & 31;
        sx[ee * 2112 + bs * 1056 + row * 33 + q] =
            x[(size_t)(pos * 8 + b0 + bs) * 1024 + e0 + ee];
    }
    __syncthreads();

    float* xA = sx + ww * 2112;
    float* xB = xA + 1056;
    const float* kg = g_ksum + (size_t)(e0 + ww) * 1024;  // 4KB, L1-resident

    float y[32], xr[32], kr[32];

    // prepass: image A, shift 0, own row
    {
        const float* px = xA + lane * 33;
#pragma unroll
        for (int c = 0; c < 32; c++) xr[c] = px[c];
        const float4* k4 = reinterpret_cast<const float4*>(kg);
#pragma unroll
        for (int c = 0; c < 8; c++) {
            float4 v = k4[c];
            kr[4*c] = v.x; kr[4*c+1] = v.y; kr[4*c+2] = v.z; kr[4*c+3] = v.w;
        }
#pragma unroll
        for (int j = 0; j < 32; j++) y[j] = kr[0] * xr[j];
#pragma unroll
        for (int dj = 1; dj < 32; dj++) {
            float kv = kr[dj];
#pragma unroll
            for (int j = dj; j < 32; j++) y[j] = fmaf(kv, xr[j - dj], y[j]);
        }
    }

    for (int di = 1; di <= 32; di++) {
        bool sw = (lane == di - 1);
        if (sw) {
            // flush completed A row `lane` into freed slot 32-di (= 31-lane)
            float* dst = xA + (32 - di) * 33;
#pragma unroll
            for (int j = 0; j < 32; j++) dst[j] = y[j];
#pragma unroll
            for (int j = 0; j < 32; j++) y[j] = 0.0f;
        }
        __syncwarp();                  // order flush STS vs other lanes' LDS
        bool isA = (lane >= di);
        int xrow = isA ? (lane - di) : (di - 1 - lane);
        const float* px = (isA ? xA : xB) + xrow * 33;
        int krow = isA ? di : (32 - di);     // di=32: all lanes B, krow=0
        const float4* k4 = reinterpret_cast<const float4*>(kg + krow * 32);
#pragma unroll
        for (int c = 0; c < 32; c++) xr[c] = px[c];
#pragma unroll
        for (int c = 0; c < 8; c++) {
            float4 v = k4[c];
            kr[4*c] = v.x; kr[4*c+1] = v.y; kr[4*c+2] = v.z; kr[4*c+3] = v.w;
        }
#pragma unroll
        for (int dj = 0; dj < 32; dj++) {
            float kv = kr[dj];
#pragma unroll
            for (int j = dj; j < 32; j++) y[j] = fmaf(kv, xr[j - dj], y[j]);
        }
    }
    __syncwarp();
    // lane holds B row 31-lane -> slot lane (same reversed convention as A)
    {
        float* dst = xB + lane * 33;
#pragma unroll
        for (int j = 0; j < 32; j++) dst[j] = y[j];
    }
    __syncthreads();

    // coalesced writeback + residual (fresh x read); rows stored reversed
    float om0 = omega[e0], om1 = omega[e0 + 1];
    for (int idx = tid; idx < 4096; idx += 64) {
        int ee = idx & 1, bs = (idx >> 1) & 1, pos = idx >> 2;
        int row = pos >> 5, q = pos & 31;
        float om = ee ? om1 : om0;
        size_t ga = (size_t)(pos * 8 + b0 + bs) * 1024 + e0 + ee;
        out[ga] = sx[ee * 2112 + bs * 1056 + (31 - row) * 33 + q] + om * x[ga];
    }
}

// ---------------- launch ----------------
extern "C" void kernel_launch(void* const* d_in, const int* in_sizes, int n_in,
                              void* d_out, int out_size) {
    const float* x     = (const float*)d_in[0];
    const float* A     = (const float*)d_in[1];
    const float* B1    = (const float*)d_in[2];
    const float* B2    = (const float*)d_in[3];
    const float* C1    = (const float*)d_in[4];
    const float* C2    = (const float*)d_in[5];
    const float* omega = (const float*)d_in[6];
    const float* onem  = (const float*)d_in[7];
    float* out = (float*)d_out;

    k_init  <<<1152, 256>>>(A, B1, B2, C1, C2, onem); // prep(512) + decode(640)
    k_w     <<<2048, 1024>>>();            // (d,p) blocks x (kd,n) threads
    k_gemm  <<<2048, 256>>>();             // 64 kd x 32 p-tiles of 32
    k_asm   <<<1024, 256>>>();             // per-embed-channel assembly
    k_conv  <<<2048, 64>>>(x, omega, out); // complementary-mask packed conv
}